// round 9
// baseline (speedup 1.0000x reference)
#include <cuda_runtime.h>
#include <cuda_bf16.h>
#include <cstdint>

// Z[b,w,t] = sum_c Q[b,w,c] * ( K[b,w+t,c] + bias[c,t] ),  B=16, T=1024, C=128.
//
// Fused per-tile kernel (128x128), software-pipelined:
//  - band GEMM ksteps 0-3 (c-low) overlap conversion of reg-prefetched panel c-high
//  - band GEMM ksteps 4-7 (c-high) overlap bias gather LDGs
//  - scatter band acc -> smem Z overlay; bias GEMM; fused STG epilogue.
// GEMMs: merged k-loop AhBh + AhBl + AlBh (bf16 hi/lo split, fp32 accum).

#define TDIM   1024
#define CDIM   128
#define KROWS  2047
#define NTHREADS 512

// ---- smem layout (bytes) ----
#define OQH 0
#define OQL 32768
#define OPH 65536                       // K panel hi (272 rows x 256B)
#define PANEL_BYTES (272 * 256)         // 69632
#define OPL (OPH + PANEL_BYTES)         // 135168  K panel lo
#define SMEM_BYTES (OPL + PANEL_BYTES)  // 204800
// overlays (valid after band GEMM):
#define OZS OPH                         // fp32 Z buffer, 128 x ZSTRIDE (67584 <= 69632)
#define ZSTRIDE 132
#define OBH OPL                         // bias B hi (128 x 256B)
#define OBL (OPL + 32768)               // bias B lo

__device__ __forceinline__ void ldsm4(uint32_t addr, uint32_t& r0, uint32_t& r1,
                                      uint32_t& r2, uint32_t& r3) {
    asm volatile("ldmatrix.sync.aligned.m8n8.x4.shared.b16 {%0,%1,%2,%3}, [%4];"
                 : "=r"(r0), "=r"(r1), "=r"(r2), "=r"(r3) : "r"(addr));
}
__device__ __forceinline__ void mma16816(float* d, uint32_t a0, uint32_t a1,
                                         uint32_t a2, uint32_t a3,
                                         uint32_t b0, uint32_t b1) {
    asm volatile("mma.sync.aligned.m16n8k16.row.col.f32.bf16.bf16.f32 "
                 "{%0,%1,%2,%3}, {%4,%5,%6,%7}, {%8,%9}, {%0,%1,%2,%3};"
                 : "+f"(d[0]), "+f"(d[1]), "+f"(d[2]), "+f"(d[3])
                 : "r"(a0), "r"(a1), "r"(a2), "r"(a3), "r"(b0), "r"(b1));
}
__device__ __forceinline__ uint32_t smem_u32(const void* p) {
    uint32_t a;
    asm("{ .reg .u64 t; cvta.to.shared.u64 t, %1; cvt.u32.u64 %0, t; }" : "=r"(a) : "l"(p));
    return a;
}
__device__ __forceinline__ uint32_t pack_hi_lo(float x, float y, uint32_t& lo_out) {
    __nv_bfloat16 hx = __float2bfloat16(x);
    __nv_bfloat16 hy = __float2bfloat16(y);
    __nv_bfloat16 lx = __float2bfloat16(x - __bfloat162float(hx));
    __nv_bfloat16 ly = __float2bfloat16(y - __bfloat162float(hy));
    __nv_bfloat162 h = __nv_bfloat162(hx, hy);
    __nv_bfloat162 l = __nv_bfloat162(lx, ly);
    lo_out = *reinterpret_cast<uint32_t*>(&l);
    return *reinterpret_cast<uint32_t*>(&h);
}
// store float4 (4 c-values) of row `row` at c = cv*4 into hi/lo bf16 buffers
__device__ __forceinline__ void st_hilo4(char* sm, int bufH, int bufL,
                                         int row, int cv, float4 v) {
    uint32_t l01, l23;
    uint32_t h01 = pack_hi_lo(v.x, v.y, l01);
    uint32_t h23 = pack_hi_lo(v.z, v.w, l23);
    int c2 = cv >> 1;
    uint32_t off = (uint32_t)(row * 256 + (((c2) ^ (row & 7)) << 4) + (cv & 1) * 8);
    *reinterpret_cast<uint2*>(sm + bufH + off) = make_uint2(h01, h23);
    *reinterpret_cast<uint2*>(sm + bufL + off) = make_uint2(l01, l23);
}

__global__ __launch_bounds__(NTHREADS, 1)
void sw_fused_kernel(const float* __restrict__ Q,
                     const float* __restrict__ Km,
                     const float* __restrict__ bias,
                     float* __restrict__ Z)
{
    extern __shared__ char smem[];
    const uint32_t sb = smem_u32(smem);
    float* zs = reinterpret_cast<float*>(smem + OZS);

    const int tid  = threadIdx.x;
    const int wid  = tid >> 5;
    const int lane = tid & 31;

    const int b  = blockIdx.z;
    const int w0 = blockIdx.y * 128;
    const int t0 = blockIdx.x * 128;
    const int u0 = w0 + t0;

    const float* Qb = Q  + ((size_t)b * TDIM) * CDIM;
    const float* Kb = Km + ((size_t)b * KROWS) * CDIM;
    float* Zb = Z + ((size_t)b * TDIM + w0) * TDIM + t0;

    const uint32_t rx  = lane & 7;
    const uint32_t aC2 = lane >> 4;
    const uint32_t bC2 = (lane >> 3) & 1;
    const int er = lane >> 2;
    const int ec = (lane & 3) * 2;

    // ========= phase 0: prefetch panel c-high rows 0..255 into regs =========
    float4 preg[8];
#pragma unroll
    for (int r = 0; r < 8; r++) {
        int idx = tid + NTHREADS * r;           // 0..4095
        int row = idx >> 4;                     // 0..255
        int cv  = 16 + (idx & 15);              // c-high
        int u = u0 + row; if (u > 2046) u = 2046;
        preg[r] = *reinterpret_cast<const float4*>(Kb + (size_t)u * CDIM + cv * 4);
    }

    // ========= phase 1: stage Q (full) =========
#pragma unroll
    for (int r = 0; r < 8; r++) {
        int idx = tid + NTHREADS * r;           // 4096 float4
        int row = idx >> 5, cv = idx & 31;
        float4 v = *reinterpret_cast<const float4*>(Qb + (size_t)(w0 + row) * CDIM + cv * 4);
        st_hilo4(smem, OQH, OQL, row, cv, v);
    }
    // panel c-low rows 0..271 (4352 items) + c-high rows 256..271 (256 items) = 4608
#pragma unroll
    for (int r = 0; r < 9; r++) {
        int idx = tid + NTHREADS * r;           // 0..4607
        int row, cv;
        if (idx < 4352) { row = idx >> 4; cv = idx & 15; }
        else { int j = idx - 4352; row = 256 + (j >> 4); cv = 16 + (j & 15); }
        int u = u0 + row; if (u > 2046) u = 2046;
        float4 v = *reinterpret_cast<const float4*>(Kb + (size_t)u * CDIM + cv * 4);
        st_hilo4(smem, OPH, OPL, row, cv, v);
    }
    __syncthreads();

    // ===================== band GEMM =====================
    {
        const int mt = wid >> 1;
        const int h  = wid & 1;
        const int im = mt * 16;
        const uint32_t aRowB = (uint32_t)((im + (lane & 15)) * 256);
        uint32_t bRowG[5];
#pragma unroll
        for (int g = 0; g < 5; g++)
            bRowG[g] = (uint32_t)((im + 80 * h + 16 * g + ((lane >> 4) << 3) + (lane & 7)) * 256);

        float acc[10][4];
#pragma unroll
        for (int n = 0; n < 10; n++)
#pragma unroll
            for (int e = 0; e < 4; e++) acc[n][e] = 0.f;

#define BAND_KSTEP(ST) do {                                                  \
        uint32_t kc = 2u * (uint32_t)(ST);                                   \
        uint32_t aoff = ((kc + aC2) ^ rx) << 4;                              \
        uint32_t boff = ((kc + bC2) ^ rx) << 4;                              \
        uint32_t ah0,ah1,ah2,ah3, al0,al1,al2,al3;                           \
        ldsm4(sb + OQH + aRowB + aoff, ah0,ah1,ah2,ah3);                     \
        ldsm4(sb + OQL + aRowB + aoff, al0,al1,al2,al3);                     \
        _Pragma("unroll")                                                    \
        for (int g = 0; g < 5; g++) {                                        \
            uint32_t bh0,bh1,bh2,bh3, bl0,bl1,bl2,bl3;                       \
            ldsm4(sb + OPH + bRowG[g] + boff, bh0,bh1,bh2,bh3);              \
            ldsm4(sb + OPL + bRowG[g] + boff, bl0,bl1,bl2,bl3);              \
            mma16816(acc[2*g    ], ah0,ah1,ah2,ah3, bh0,bh1);                \
            mma16816(acc[2*g + 1], ah0,ah1,ah2,ah3, bh2,bh3);                \
            mma16816(acc[2*g    ], ah0,ah1,ah2,ah3, bl0,bl1);                \
            mma16816(acc[2*g + 1], ah0,ah1,ah2,ah3, bl2,bl3);                \
            mma16816(acc[2*g    ], al0,al1,al2,al3, bh0,bh1);                \
            mma16816(acc[2*g + 1], al0,al1,al2,al3, bh2,bh3);                \
        }                                                                    \
} while (0)

        // ---- ksteps 0..3 (c-low) with interleaved c-high convert+STS ----
#pragma unroll
        for (int st = 0; st < 4; st++) {
            BAND_KSTEP(st);
#pragma unroll
            for (int q = 0; q < 2; q++) {
                int r = 2 * st + q;
                int idx = tid + NTHREADS * r;
                st_hilo4(smem, OPH, OPL, idx >> 4, 16 + (idx & 15), preg[r]);
            }
        }
        __syncthreads();   // c-high staged before ksteps 4..7 read it

        // ---- prefetch bias gather (drains under ksteps 4..7) ----
        const int btau = tid >> 2;
        const int bcb  = (tid & 3) * 32;
        float f[32];
#pragma unroll
        for (int j = 0; j < 32; j++)
            f[j] = __ldg(bias + (size_t)(bcb + j) * TDIM + t0 + btau);

        // ---- ksteps 4..7 (c-high) ----
#pragma unroll
        for (int st = 4; st < 8; st++) {
            BAND_KSTEP(st);
        }
#undef BAND_KSTEP

        __syncthreads();   // all panel reads done before overlays are written

        // ---- scatter (pure assignment): zs[im+r, j-r] = D[r, j] ----
#pragma unroll
        for (int nf = 0; nf < 10; nf++)
#pragma unroll
            for (int e = 0; e < 4; e++) {
                int r = er + ((e & 2) ? 8 : 0);
                int j = 80 * h + nf * 8 + ec + (e & 1);
                int tau = j - r;
                if ((unsigned)tau < 128u)
                    zs[(im + r) * ZSTRIDE + tau] = acc[nf][e];
            }

        // ---- convert bias regs -> B buffers (overlay on panel-lo) ----
#pragma unroll
        for (int j = 0; j < 16; j++) {
            uint32_t lo;
            uint32_t hi = pack_hi_lo(f[2 * j], f[2 * j + 1], lo);
            int c = bcb + 2 * j;
            int c2 = c >> 3;
            uint32_t off = (uint32_t)(btau * 256 + ((c2 ^ (btau & 7)) << 4) + ((c * 2) & 15));
            *reinterpret_cast<uint32_t*>(smem + OBH + off) = hi;
            *reinterpret_cast<uint32_t*>(smem + OBL + off) = lo;
        }
    }
    __syncthreads();

    // ===================== bias GEMM + fused epilogue =====================
    {
        const int wr = wid >> 2;            // 0..3
        const int wc = wid & 3;             // 0..3
        uint32_t aRow[2], bRow[2];
#pragma unroll
        for (int mt = 0; mt < 2; mt++)
            aRow[mt] = (uint32_t)((wr * 32 + mt * 16 + (lane & 15)) * 256);
#pragma unroll
        for (int p = 0; p < 2; p++)
            bRow[p] = (uint32_t)((wc * 32 + p * 16 + ((lane >> 4) << 3) + (lane & 7)) * 256);

        float acc[2][4][4];
#pragma unroll
        for (int m = 0; m < 2; m++)
#pragma unroll
            for (int n = 0; n < 4; n++)
#pragma unroll
                for (int e = 0; e < 4; e++) acc[m][n][e] = 0.f;

#pragma unroll
        for (int st = 0; st < 8; st++) {
            uint32_t kc = 2u * (uint32_t)st;
            uint32_t aoff = ((kc + aC2) ^ rx) << 4;
            uint32_t boff = ((kc + bC2) ^ rx) << 4;
            uint32_t ah0,ah1,ah2,ah3,ah4,ah5,ah6,ah7;
            uint32_t al0,al1,al2,al3,al4,al5,al6,al7;
            uint32_t bh0,bh1,bh2,bh3,bh4,bh5,bh6,bh7;
            uint32_t bl0,bl1,bl2,bl3,bl4,bl5,bl6,bl7;
            ldsm4(sb + OQH + aRow[0] + aoff, ah0,ah1,ah2,ah3);
            ldsm4(sb + OQH + aRow[1] + aoff, ah4,ah5,ah6,ah7);
            ldsm4(sb + OQL + aRow[0] + aoff, al0,al1,al2,al3);
            ldsm4(sb + OQL + aRow[1] + aoff, al4,al5,al6,al7);
            ldsm4(sb + OBH + bRow[0] + boff, bh0,bh1,bh2,bh3);
            ldsm4(sb + OBH + bRow[1] + boff, bh4,bh5,bh6,bh7);
            ldsm4(sb + OBL + bRow[0] + boff, bl0,bl1,bl2,bl3);
            ldsm4(sb + OBL + bRow[1] + boff, bl4,bl5,bl6,bl7);
            mma16816(acc[0][0], ah0,ah1,ah2,ah3, bh0,bh1);
            mma16816(acc[0][1], ah0,ah1,ah2,ah3, bh2,bh3);
            mma16816(acc[0][2], ah0,ah1,ah2,ah3, bh4,bh5);
            mma16816(acc[0][3], ah0,ah1,ah2,ah3, bh6,bh7);
            mma16816(acc[1][0], ah4,ah5,ah6,ah7, bh0,bh1);
            mma16816(acc[1][1], ah4,ah5,ah6,ah7, bh2,bh3);
            mma16816(acc[1][2], ah4,ah5,ah6,ah7, bh4,bh5);
            mma16816(acc[1][3], ah4,ah5,ah6,ah7, bh6,bh7);
            mma16816(acc[0][0], ah0,ah1,ah2,ah3, bl0,bl1);
            mma16816(acc[0][1], ah0,ah1,ah2,ah3, bl2,bl3);
            mma16816(acc[0][2], ah0,ah1,ah2,ah3, bl4,bl5);
            mma16816(acc[0][3], ah0,ah1,ah2,ah3, bl6,bl7);
            mma16816(acc[1][0], ah4,ah5,ah6,ah7, bl0,bl1);
            mma16816(acc[1][1], ah4,ah5,ah6,ah7, bl2,bl3);
            mma16816(acc[1][2], ah4,ah5,ah6,ah7, bl4,bl5);
            mma16816(acc[1][3], ah4,ah5,ah6,ah7, bl6,bl7);
            mma16816(acc[0][0], al0,al1,al2,al3, bh0,bh1);
            mma16816(acc[0][1], al0,al1,al2,al3, bh2,bh3);
            mma16816(acc[0][2], al0,al1,al2,al3, bh4,bh5);
            mma16816(acc[0][3], al0,al1,al2,al3, bh6,bh7);
            mma16816(acc[1][0], al4,al5,al6,al7, bh0,bh1);
            mma16816(acc[1][1], al4,al5,al6,al7, bh2,bh3);
            mma16816(acc[1][2], al4,al5,al6,al7, bh4,bh5);
            mma16816(acc[1][3], al4,al5,al6,al7, bh6,bh7);
        }

        // ---- epilogue: Z = zs + PB, direct STG ----
#pragma unroll
        for (int mt = 0; mt < 2; mt++)
#pragma unroll
            for (int nt = 0; nt < 4; nt++) {
                int i0  = wr * 32 + mt * 16 + er;
                int tau = wc * 32 + nt * 8 + ec;
                const float* z0 = zs + i0 * ZSTRIDE + tau;
                const float* z1 = zs + (i0 + 8) * ZSTRIDE + tau;
                *reinterpret_cast<float2*>(Zb + (size_t)i0 * TDIM + tau) =
                    make_float2(acc[mt][nt][0] + z0[0], acc[mt][nt][1] + z0[1]);
                *reinterpret_cast<float2*>(Zb + (size_t)(i0 + 8) * TDIM + tau) =
                    make_float2(acc[mt][nt][2] + z1[0], acc[mt][nt][3] + z1[1]);
            }
    }
}

extern "C" void kernel_launch(void* const* d_in, const int* in_sizes, int n_in,
                              void* d_out, int out_size)
{
    const float* Q    = (const float*)d_in[0];   // (16, 1024, 128)
    const float* Km   = (const float*)d_in[1];   // (16, 2047, 128)
    const float* bias = (const float*)d_in[2];   // (1, 1, 128, 1024)
    float* Z          = (float*)d_out;           // (16, 1024, 1024)

    cudaFuncSetAttribute(sw_fused_kernel, cudaFuncAttributeMaxDynamicSharedMemorySize, SMEM_BYTES);
    dim3 grid(TDIM / 128, TDIM / 128, 16);       // (8, 8, 16) = 1024 CTAs
    sw_fused_kernel<<<grid, NTHREADS, SMEM_BYTES>>>(Q, Km, bias, Z);
}

// round 10
// speedup vs baseline: 1.3829x; 1.3829x over previous
#include <cuda_runtime.h>
#include <cuda_fp16.h>
#include <cstdint>

// Z[b,w,t] = sum_c Q[b,w,c] * ( K[b,w+t,c] + bias[c,t] ),  B=16, T=1024, C=128.
//
// Fused per-tile kernel (128x128), fp16 2-pass split:
//   Qh = fp16(Q), Ql = fp16(Q - Qh);  B (K panel / bias) = fp16 single.
//   Z = Qh*B + Ql*B  (fp32 accum) -> rel err ~ 2^-12-ish (norm ~1e-4).
//  1) band GEMM: per warp (mt = wid>>1, h = wid&1), rows [16mt,16mt+16):
//       D[r,j] = sum_c Q[w0+16mt+r, c] * K[u0+16mt+j, c], j in [80h, 80h+80)
//     scatter-assign D[r,j] -> zs[16mt+r, j-r]  (0 <= j-r < 128; disjoint)
//  2) bias GEMM: PB[i,s] = sum_c Q[w0+i,c] * bias[c, t0+s]
//     epilogue: Z[w0+i, t0+s] = zs[i,s] + PB[i,s]   (single direct STG)

#define TDIM   1024
#define CDIM   128
#define KROWS  2047
#define NTHREADS 512

// ---- smem layout (bytes); fp16 buffers: rows of 256B, 16B chunks XOR-swizzled ----
#define OQH 0                            // Q hi  (128 x 256B)
#define OQL 32768                        // Q lo  (128 x 256B)
#define OPH 65536                        // K panel (272 x 256B), single fp16
#define PANEL_BYTES (272 * 256)          // 69632
#define OBH (OPH + PANEL_BYTES)          // bias B (128 x 256B), single fp16
#define SMEM_BYTES (OBH + 32768)         // 167936
// overlay (valid after band GEMM): fp32 Z buffer over the panel region
#define OZS OPH
#define ZSTRIDE 132                      // 128*132*4 = 67584 <= 69632

__device__ __forceinline__ void ldsm4(uint32_t addr, uint32_t& r0, uint32_t& r1,
                                      uint32_t& r2, uint32_t& r3) {
    asm volatile("ldmatrix.sync.aligned.m8n8.x4.shared.b16 {%0,%1,%2,%3}, [%4];"
                 : "=r"(r0), "=r"(r1), "=r"(r2), "=r"(r3) : "r"(addr));
}
__device__ __forceinline__ void mma16816(float* d, uint32_t a0, uint32_t a1,
                                         uint32_t a2, uint32_t a3,
                                         uint32_t b0, uint32_t b1) {
    asm volatile("mma.sync.aligned.m16n8k16.row.col.f32.f16.f16.f32 "
                 "{%0,%1,%2,%3}, {%4,%5,%6,%7}, {%8,%9}, {%0,%1,%2,%3};"
                 : "+f"(d[0]), "+f"(d[1]), "+f"(d[2]), "+f"(d[3])
                 : "r"(a0), "r"(a1), "r"(a2), "r"(a3), "r"(b0), "r"(b1));
}
__device__ __forceinline__ uint32_t smem_u32(const void* p) {
    uint32_t a;
    asm("{ .reg .u64 t; cvta.to.shared.u64 t, %1; cvt.u32.u64 %0, t; }" : "=r"(a) : "l"(p));
    return a;
}
__device__ __forceinline__ uint32_t pack_h2(float x, float y) {
    __half2 h = __halves2half2(__float2half_rn(x), __float2half_rn(y));
    return *reinterpret_cast<uint32_t*>(&h);
}
// Q split: hi = fp16(x), lo = fp16(x - hi)
__device__ __forceinline__ uint32_t pack_qsplit(float x, float y, uint32_t& lo_out) {
    __half hx = __float2half_rn(x);
    __half hy = __float2half_rn(y);
    __half lx = __float2half_rn(x - __half2float(hx));
    __half ly = __float2half_rn(y - __half2float(hy));
    __half2 h = __halves2half2(hx, hy);
    __half2 l = __halves2half2(lx, ly);
    lo_out = *reinterpret_cast<uint32_t*>(&l);
    return *reinterpret_cast<uint32_t*>(&h);
}
// swizzled byte offset for (row, cv) with cv = float4 index (4 c-values -> 8B fp16)
__device__ __forceinline__ uint32_t sw_off(int row, int cv) {
    int c2 = cv >> 1;
    return (uint32_t)(row * 256 + (((c2) ^ (row & 7)) << 4) + (cv & 1) * 8);
}
// store 4 c-values split into hi/lo Q buffers
__device__ __forceinline__ void st_q4(char* sm, int row, int cv, float4 v) {
    uint32_t l01, l23;
    uint32_t h01 = pack_qsplit(v.x, v.y, l01);
    uint32_t h23 = pack_qsplit(v.z, v.w, l23);
    uint32_t off = sw_off(row, cv);
    *reinterpret_cast<uint2*>(sm + OQH + off) = make_uint2(h01, h23);
    *reinterpret_cast<uint2*>(sm + OQL + off) = make_uint2(l01, l23);
}
// store 4 c-values single fp16 into buffer `buf`
__device__ __forceinline__ void st_s4(char* sm, int buf, int row, int cv, float4 v) {
    uint32_t off = sw_off(row, cv);
    *reinterpret_cast<uint2*>(sm + buf + off) =
        make_uint2(pack_h2(v.x, v.y), pack_h2(v.z, v.w));
}

__global__ __launch_bounds__(NTHREADS, 1)
void sw_fused_kernel(const float* __restrict__ Q,
                     const float* __restrict__ Km,
                     const float* __restrict__ bias,
                     float* __restrict__ Z)
{
    extern __shared__ char smem[];
    const uint32_t sb = smem_u32(smem);
    float* zs = reinterpret_cast<float*>(smem + OZS);

    const int tid  = threadIdx.x;
    const int wid  = tid >> 5;
    const int lane = tid & 31;

    const int b  = blockIdx.z;
    const int w0 = blockIdx.y * 128;
    const int t0 = blockIdx.x * 128;
    const int u0 = w0 + t0;

    const float* Qb = Q  + ((size_t)b * TDIM) * CDIM;
    const float* Kb = Km + ((size_t)b * KROWS) * CDIM;
    float* Zb = Z + ((size_t)b * TDIM + w0) * TDIM + t0;

    const uint32_t rx  = lane & 7;
    const uint32_t aC2 = lane >> 4;
    const uint32_t bC2 = (lane >> 3) & 1;
    const int er = lane >> 2;
    const int ec = (lane & 3) * 2;

    // ===================== stage Q (fp16 hi/lo split) =====================
#pragma unroll
    for (int r = 0; r < 8; r++) {
        int idx = tid + NTHREADS * r;           // 4096 float4
        int row = idx >> 5, cv = idx & 31;
        float4 v = *reinterpret_cast<const float4*>(Qb + (size_t)(w0 + row) * CDIM + cv * 4);
        st_q4(smem, row, cv, v);
    }
    // ===================== stage K panel (272 rows, single fp16) =====================
#pragma unroll
    for (int r = 0; r < 17; r++) {
        int idx = tid + NTHREADS * r;           // 8704 = 272*32 exactly
        int row = idx >> 5, cv = idx & 31;
        int u = u0 + row;
        if (u > 2046) u = 2046;                 // clamped rows only feed discarded taus
        float4 v = *reinterpret_cast<const float4*>(Kb + (size_t)u * CDIM + cv * 4);
        st_s4(smem, OPH, row, cv, v);
    }
    // ===================== stage bias (single fp16, own region) =====================
    {
        const int btau = tid >> 2;
        const int bcb  = (tid & 3) * 32;
        float f[32];
#pragma unroll
        for (int j = 0; j < 32; j++)
            f[j] = __ldg(bias + (size_t)(bcb + j) * TDIM + t0 + btau);
#pragma unroll
        for (int j = 0; j < 16; j++) {
            uint32_t hv = pack_h2(f[2 * j], f[2 * j + 1]);
            int c = bcb + 2 * j;
            int c2 = c >> 3;
            uint32_t off = (uint32_t)(btau * 256 + ((c2 ^ (btau & 7)) << 4) + ((c * 2) & 15));
            *reinterpret_cast<uint32_t*>(smem + OBH + off) = hv;
        }
    }
    __syncthreads();

    // ===================== band GEMM (2-pass) =====================
    {
        const int mt = wid >> 1;
        const int h  = wid & 1;
        const int im = mt * 16;
        const uint32_t aRowB = (uint32_t)((im + (lane & 15)) * 256);
        uint32_t bRowG[5];
#pragma unroll
        for (int g = 0; g < 5; g++)
            bRowG[g] = (uint32_t)((im + 80 * h + 16 * g + ((lane >> 4) << 3) + (lane & 7)) * 256);

        float acc[10][4];
#pragma unroll
        for (int n = 0; n < 10; n++)
#pragma unroll
            for (int e = 0; e < 4; e++) acc[n][e] = 0.f;

#pragma unroll
        for (int st = 0; st < 8; st++) {
            uint32_t kc = 2u * (uint32_t)st;
            uint32_t aoff = ((kc + aC2) ^ rx) << 4;
            uint32_t boff = ((kc + bC2) ^ rx) << 4;
            uint32_t ah0,ah1,ah2,ah3, al0,al1,al2,al3;
            ldsm4(sb + OQH + aRowB + aoff, ah0,ah1,ah2,ah3);
            ldsm4(sb + OQL + aRowB + aoff, al0,al1,al2,al3);
#pragma unroll
            for (int g = 0; g < 5; g++) {
                uint32_t b0,b1,b2,b3;
                ldsm4(sb + OPH + bRowG[g] + boff, b0,b1,b2,b3);
                mma16816(acc[2*g    ], ah0,ah1,ah2,ah3, b0,b1);
                mma16816(acc[2*g + 1], ah0,ah1,ah2,ah3, b2,b3);
                mma16816(acc[2*g    ], al0,al1,al2,al3, b0,b1);
                mma16816(acc[2*g + 1], al0,al1,al2,al3, b2,b3);
            }
        }
        __syncthreads();   // all panel reads done before zs overlay is written

        // ---- scatter (pure assignment): zs[im+r, j-r] = D[r, j] ----
#pragma unroll
        for (int nf = 0; nf < 10; nf++)
#pragma unroll
            for (int e = 0; e < 4; e++) {
                int r = er + ((e & 2) ? 8 : 0);
                int j = 80 * h + nf * 8 + ec + (e & 1);
                int tau = j - r;
                if ((unsigned)tau < 128u)
                    zs[(im + r) * ZSTRIDE + tau] = acc[nf][e];
            }
    }
    __syncthreads();

    // ===================== bias GEMM (2-pass) + fused epilogue =====================
    {
        const int wr = wid >> 2;            // 0..3
        const int wc = wid & 3;             // 0..3
        uint32_t aRow[2], bRow[2];
#pragma unroll
        for (int mt = 0; mt < 2; mt++)
            aRow[mt] = (uint32_t)((wr * 32 + mt * 16 + (lane & 15)) * 256);
#pragma unroll
        for (int p = 0; p < 2; p++)
            bRow[p] = (uint32_t)((wc * 32 + p * 16 + ((lane >> 4) << 3) + (lane & 7)) * 256);

        float acc[2][4][4];
#pragma unroll
        for (int m = 0; m < 2; m++)
#pragma unroll
            for (int n = 0; n < 4; n++)
#pragma unroll
                for (int e = 0; e < 4; e++) acc[m][n][e] = 0.f;

#pragma unroll
        for (int st = 0; st < 8; st++) {
            uint32_t kc = 2u * (uint32_t)st;
            uint32_t aoff = ((kc + aC2) ^ rx) << 4;
            uint32_t boff = ((kc + bC2) ^ rx) << 4;
            uint32_t ah0,ah1,ah2,ah3,ah4,ah5,ah6,ah7;
            uint32_t al0,al1,al2,al3,al4,al5,al6,al7;
            uint32_t b0,b1,b2,b3,b4,b5,b6,b7;
            ldsm4(sb + OQH + aRow[0] + aoff, ah0,ah1,ah2,ah3);
            ldsm4(sb + OQH + aRow[1] + aoff, ah4,ah5,ah6,ah7);
            ldsm4(sb + OQL + aRow[0] + aoff, al0,al1,al2,al3);
            ldsm4(sb + OQL + aRow[1] + aoff, al4,al5,al6,al7);
            ldsm4(sb + OBH + bRow[0] + boff, b0,b1,b2,b3);
            ldsm4(sb + OBH + bRow[1] + boff, b4,b5,b6,b7);
            mma16816(acc[0][0], ah0,ah1,ah2,ah3, b0,b1);
            mma16816(acc[0][1], ah0,ah1,ah2,ah3, b2,b3);
            mma16816(acc[0][2], ah0,ah1,ah2,ah3, b4,b5);
            mma16816(acc[0][3], ah0,ah1,ah2,ah3, b6,b7);
            mma16816(acc[1][0], ah4,ah5,ah6,ah7, b0,b1);
            mma16816(acc[1][1], ah4,ah5,ah6,ah7, b2,b3);
            mma16816(acc[1][2], ah4,ah5,ah6,ah7, b4,b5);
            mma16816(acc[1][3], ah4,ah5,ah6,ah7, b6,b7);
            mma16816(acc[0][0], al0,al1,al2,al3, b0,b1);
            mma16816(acc[0][1], al0,al1,al2,al3, b2,b3);
            mma16816(acc[0][2], al0,al1,al2,al3, b4,b5);
            mma16816(acc[0][3], al0,al1,al2,al3, b6,b7);
            mma16816(acc[1][0], al4,al5,al6,al7, b0,b1);
            mma16816(acc[1][1], al4,al5,al6,al7, b2,b3);
            mma16816(acc[1][2], al4,al5,al6,al7, b4,b5);
            mma16816(acc[1][3], al4,al5,al6,al7, b6,b7);
        }

        // ---- epilogue: Z = zs + PB, direct STG ----
#pragma unroll
        for (int mt = 0; mt < 2; mt++)
#pragma unroll
            for (int nt = 0; nt < 4; nt++) {
                int i0  = wr * 32 + mt * 16 + er;
                int tau = wc * 32 + nt * 8 + ec;
                const float* z0 = zs + i0 * ZSTRIDE + tau;
                const float* z1 = zs + (i0 + 8) * ZSTRIDE + tau;
                *reinterpret_cast<float2*>(Zb + (size_t)i0 * TDIM + tau) =
                    make_float2(acc[mt][nt][0] + z0[0], acc[mt][nt][1] + z0[1]);
                *reinterpret_cast<float2*>(Zb + (size_t)(i0 + 8) * TDIM + tau) =
                    make_float2(acc[mt][nt][2] + z1[0], acc[mt][nt][3] + z1[1]);
            }
    }
}

extern "C" void kernel_launch(void* const* d_in, const int* in_sizes, int n_in,
                              void* d_out, int out_size)
{
    const float* Q    = (const float*)d_in[0];   // (16, 1024, 128)
    const float* Km   = (const float*)d_in[1];   // (16, 2047, 128)
    const float* bias = (const float*)d_in[2];   // (1, 1, 128, 1024)
    float* Z          = (float*)d_out;           // (16, 1024, 1024)

    cudaFuncSetAttribute(sw_fused_kernel, cudaFuncAttributeMaxDynamicSharedMemorySize, SMEM_BYTES);
    dim3 grid(TDIM / 128, TDIM / 128, 16);       // (8, 8, 16) = 1024 CTAs
    sw_fused_kernel<<<grid, NTHREADS, SMEM_BYTES>>>(Q, Km, bias, Z);
}

// round 11
// speedup vs baseline: 1.7697x; 1.2797x over previous
#include <cuda_runtime.h>
#include <cuda_fp16.h>
#include <cstdint>

// Z[b,w,t] = sum_c Q[b,w,c] * ( K[b,w+t,c] + bias[c,t] ),  B=16, T=1024, C=128.
//
// Fused per-tile kernel (128x128), SINGLE-pass fp16:
//   Qh = fp16(Q); B (K panel / bias) = fp16.  Z = Qh*B (fp32 accum).
//   rel err ~ sqrt(2) * 2^-12-ish (norm ~3e-4 < 1e-3).
//  1) band GEMM: per warp (mt = wid>>1, h = wid&1), rows [16mt,16mt+16):
//       D[r,j] = sum_c Q[w0+16mt+r, c] * K[u0+16mt+j, c], j in [80h, 80h+80)
//     scatter-assign D[r,j] -> zs[16mt+r, j-r]  (0 <= j-r < 128; disjoint)
//  2) bias GEMM: PB[i,s] = sum_c Q[w0+i,c] * bias[c, t0+s]
//     epilogue: Z[w0+i, t0+s] = zs[i,s] + PB[i,s]   (single direct STG)

#define TDIM   1024
#define CDIM   128
#define KROWS  2047
#define NTHREADS 512

// ---- smem layout (bytes); fp16 buffers: rows of 256B, 16B chunks XOR-swizzled ----
#define OQ  0                            // Q fp16 (128 x 256B)
#define OPH 32768                        // K panel (272 x 256B)
#define PANEL_BYTES (272 * 256)          // 69632
#define OBH (OPH + PANEL_BYTES)          // bias B (128 x 256B) = 102400
#define SMEM_BYTES (OBH + 32768)         // 135168
// overlay (valid after band GEMM): fp32 Z buffer over the panel region
#define OZS OPH
#define ZSTRIDE 132                      // 128*132*4 = 67584 <= 69632

__device__ __forceinline__ void ldsm4(uint32_t addr, uint32_t& r0, uint32_t& r1,
                                      uint32_t& r2, uint32_t& r3) {
    asm volatile("ldmatrix.sync.aligned.m8n8.x4.shared.b16 {%0,%1,%2,%3}, [%4];"
                 : "=r"(r0), "=r"(r1), "=r"(r2), "=r"(r3) : "r"(addr));
}
__device__ __forceinline__ void mma16816(float* d, uint32_t a0, uint32_t a1,
                                         uint32_t a2, uint32_t a3,
                                         uint32_t b0, uint32_t b1) {
    asm volatile("mma.sync.aligned.m16n8k16.row.col.f32.f16.f16.f32 "
                 "{%0,%1,%2,%3}, {%4,%5,%6,%7}, {%8,%9}, {%0,%1,%2,%3};"
                 : "+f"(d[0]), "+f"(d[1]), "+f"(d[2]), "+f"(d[3])
                 : "r"(a0), "r"(a1), "r"(a2), "r"(a3), "r"(b0), "r"(b1));
}
__device__ __forceinline__ uint32_t smem_u32(const void* p) {
    uint32_t a;
    asm("{ .reg .u64 t; cvta.to.shared.u64 t, %1; cvt.u32.u64 %0, t; }" : "=r"(a) : "l"(p));
    return a;
}
__device__ __forceinline__ uint32_t pack_h2(float x, float y) {
    __half2 h = __halves2half2(__float2half_rn(x), __float2half_rn(y));
    return *reinterpret_cast<uint32_t*>(&h);
}
// swizzled byte offset for (row, cv) with cv = float4 index (4 c-values -> 8B fp16)
__device__ __forceinline__ uint32_t sw_off(int row, int cv) {
    int c2 = cv >> 1;
    return (uint32_t)(row * 256 + (((c2) ^ (row & 7)) << 4) + (cv & 1) * 8);
}
// store 4 c-values as fp16 into buffer `buf`
__device__ __forceinline__ void st_s4(char* sm, int buf, int row, int cv, float4 v) {
    *reinterpret_cast<uint2*>(sm + buf + sw_off(row, cv)) =
        make_uint2(pack_h2(v.x, v.y), pack_h2(v.z, v.w));
}

__global__ __launch_bounds__(NTHREADS, 1)
void sw_fused_kernel(const float* __restrict__ Q,
                     const float* __restrict__ Km,
                     const float* __restrict__ bias,
                     float* __restrict__ Z)
{
    extern __shared__ char smem[];
    const uint32_t sb = smem_u32(smem);
    float* zs = reinterpret_cast<float*>(smem + OZS);

    const int tid  = threadIdx.x;
    const int wid  = tid >> 5;
    const int lane = tid & 31;

    const int b  = blockIdx.z;
    const int w0 = blockIdx.y * 128;
    const int t0 = blockIdx.x * 128;
    const int u0 = w0 + t0;

    const float* Qb = Q  + ((size_t)b * TDIM) * CDIM;
    const float* Kb = Km + ((size_t)b * KROWS) * CDIM;
    float* Zb = Z + ((size_t)b * TDIM + w0) * TDIM + t0;

    const uint32_t rx  = lane & 7;
    const uint32_t aC2 = lane >> 4;
    const uint32_t bC2 = (lane >> 3) & 1;
    const int er = lane >> 2;
    const int ec = (lane & 3) * 2;

    // ===================== stage Q (fp16) =====================
#pragma unroll
    for (int r = 0; r < 8; r++) {
        int idx = tid + NTHREADS * r;           // 4096 float4
        int row = idx >> 5, cv = idx & 31;
        float4 v = *reinterpret_cast<const float4*>(Qb + (size_t)(w0 + row) * CDIM + cv * 4);
        st_s4(smem, OQ, row, cv, v);
    }
    // ===================== stage K panel (272 rows, fp16) =====================
#pragma unroll
    for (int r = 0; r < 17; r++) {
        int idx = tid + NTHREADS * r;           // 8704 = 272*32 exactly
        int row = idx >> 5, cv = idx & 31;
        int u = u0 + row;
        if (u > 2046) u = 2046;                 // clamped rows only feed discarded taus
        float4 v = *reinterpret_cast<const float4*>(Kb + (size_t)u * CDIM + cv * 4);
        st_s4(smem, OPH, row, cv, v);
    }
    // ===================== stage bias (fp16, own region) =====================
    {
        const int btau = tid >> 2;
        const int bcb  = (tid & 3) * 32;
        float f[32];
#pragma unroll
        for (int j = 0; j < 32; j++)
            f[j] = __ldg(bias + (size_t)(bcb + j) * TDIM + t0 + btau);
#pragma unroll
        for (int j = 0; j < 16; j++) {
            uint32_t hv = pack_h2(f[2 * j], f[2 * j + 1]);
            int c = bcb + 2 * j;
            int c2 = c >> 3;
            uint32_t off = (uint32_t)(btau * 256 + ((c2 ^ (btau & 7)) << 4) + ((c * 2) & 15));
            *reinterpret_cast<uint32_t*>(smem + OBH + off) = hv;
        }
    }
    __syncthreads();

    // ===================== band GEMM (single pass) =====================
    {
        const int mt = wid >> 1;
        const int h  = wid & 1;
        const int im = mt * 16;
        const uint32_t aRowB = (uint32_t)((im + (lane & 15)) * 256);
        uint32_t bRowG[5];
#pragma unroll
        for (int g = 0; g < 5; g++)
            bRowG[g] = (uint32_t)((im + 80 * h + 16 * g + ((lane >> 4) << 3) + (lane & 7)) * 256);

        float acc[10][4];
#pragma unroll
        for (int n = 0; n < 10; n++)
#pragma unroll
            for (int e = 0; e < 4; e++) acc[n][e] = 0.f;

#pragma unroll
        for (int st = 0; st < 8; st++) {
            uint32_t kc = 2u * (uint32_t)st;
            uint32_t aoff = ((kc + aC2) ^ rx) << 4;
            uint32_t boff = ((kc + bC2) ^ rx) << 4;
            uint32_t a0,a1,a2,a3;
            ldsm4(sb + OQ + aRowB + aoff, a0,a1,a2,a3);
#pragma unroll
            for (int g = 0; g < 5; g++) {
                uint32_t b0,b1,b2,b3;
                ldsm4(sb + OPH + bRowG[g] + boff, b0,b1,b2,b3);
                mma16816(acc[2*g    ], a0,a1,a2,a3, b0,b1);
                mma16816(acc[2*g + 1], a0,a1,a2,a3, b2,b3);
            }
        }
        __syncthreads();   // all panel reads done before zs overlay is written

        // ---- scatter (pure assignment): zs[im+r, j-r] = D[r, j] ----
#pragma unroll
        for (int nf = 0; nf < 10; nf++)
#pragma unroll
            for (int e = 0; e < 4; e++) {
                int r = er + ((e & 2) ? 8 : 0);
                int j = 80 * h + nf * 8 + ec + (e & 1);
                int tau = j - r;
                if ((unsigned)tau < 128u)
                    zs[(im + r) * ZSTRIDE + tau] = acc[nf][e];
            }
    }
    __syncthreads();

    // ===================== bias GEMM (single pass) + fused epilogue =====================
    {
        const int wr = wid >> 2;            // 0..3
        const int wc = wid & 3;             // 0..3
        uint32_t aRow[2], bRow[2];
#pragma unroll
        for (int mt = 0; mt < 2; mt++)
            aRow[mt] = (uint32_t)((wr * 32 + mt * 16 + (lane & 15)) * 256);
#pragma unroll
        for (int p = 0; p < 2; p++)
            bRow[p] = (uint32_t)((wc * 32 + p * 16 + ((lane >> 4) << 3) + (lane & 7)) * 256);

        float acc[2][4][4];
#pragma unroll
        for (int m = 0; m < 2; m++)
#pragma unroll
            for (int n = 0; n < 4; n++)
#pragma unroll
                for (int e = 0; e < 4; e++) acc[m][n][e] = 0.f;

#pragma unroll
        for (int st = 0; st < 8; st++) {
            uint32_t kc = 2u * (uint32_t)st;
            uint32_t aoff = ((kc + aC2) ^ rx) << 4;
            uint32_t boff = ((kc + bC2) ^ rx) << 4;
            uint32_t a0,a1,a2,a3,a4,a5,a6,a7;
            uint32_t b0,b1,b2,b3,b4,b5,b6,b7;
            ldsm4(sb + OQ + aRow[0] + aoff, a0,a1,a2,a3);
            ldsm4(sb + OQ + aRow[1] + aoff, a4,a5,a6,a7);
            ldsm4(sb + OBH + bRow[0] + boff, b0,b1,b2,b3);
            ldsm4(sb + OBH + bRow[1] + boff, b4,b5,b6,b7);
            mma16816(acc[0][0], a0,a1,a2,a3, b0,b1);
            mma16816(acc[0][1], a0,a1,a2,a3, b2,b3);
            mma16816(acc[0][2], a0,a1,a2,a3, b4,b5);
            mma16816(acc[0][3], a0,a1,a2,a3, b6,b7);
            mma16816(acc[1][0], a4,a5,a6,a7, b0,b1);
            mma16816(acc[1][1], a4,a5,a6,a7, b2,b3);
            mma16816(acc[1][2], a4,a5,a6,a7, b4,b5);
            mma16816(acc[1][3], a4,a5,a6,a7, b6,b7);
        }

        // ---- epilogue: Z = zs + PB, direct STG ----
#pragma unroll
        for (int mt = 0; mt < 2; mt++)
#pragma unroll
            for (int nt = 0; nt < 4; nt++) {
                int i0  = wr * 32 + mt * 16 + er;
                int tau = wc * 32 + nt * 8 + ec;
                const float* z0 = zs + i0 * ZSTRIDE + tau;
                const float* z1 = zs + (i0 + 8) * ZSTRIDE + tau;
                *reinterpret_cast<float2*>(Zb + (size_t)i0 * TDIM + tau) =
                    make_float2(acc[mt][nt][0] + z0[0], acc[mt][nt][1] + z0[1]);
                *reinterpret_cast<float2*>(Zb + (size_t)(i0 + 8) * TDIM + tau) =
                    make_float2(acc[mt][nt][2] + z1[0], acc[mt][nt][3] + z1[1]);
            }
    }
}

extern "C" void kernel_launch(void* const* d_in, const int* in_sizes, int n_in,
                              void* d_out, int out_size)
{
    const float* Q    = (const float*)d_in[0];   // (16, 1024, 128)
    const float* Km   = (const float*)d_in[1];   // (16, 2047, 128)
    const float* bias = (const float*)d_in[2];   // (1, 1, 128, 1024)
    float* Z          = (float*)d_out;           // (16, 1024, 1024)

    cudaFuncSetAttribute(sw_fused_kernel, cudaFuncAttributeMaxDynamicSharedMemorySize, SMEM_BYTES);
    dim3 grid(TDIM / 128, TDIM / 128, 16);       // (8, 8, 16) = 1024 CTAs
    sw_fused_kernel<<<grid, NTHREADS, SMEM_BYTES>>>(Q, Km, bias, Z);
}